// round 6
// baseline (speedup 1.0000x reference)
#include <cuda_runtime.h>
#include <stdint.h>
#include <math.h>

#define H 64
#define WARPS 8
#define ROWS_PER_BLOCK (WARPS * 2)     // 2 rows per warp
#define THREADS (WARPS * 32)
#define MAXPART 4096

__device__ float2 g_part[MAXPART];
__device__ unsigned int g_done = 0;

__device__ __forceinline__ void pair_acc(float fri, float si, float2 q,
                                         float& acc, float& cnt)
{
    const float dr = q.x - fri;                                        // rank_j - rank_i (NaN if either invalid)
    const float sg = __int_as_float((__float_as_int(dr) & 0x80000000u) | 0x3f800000u);
    const float t  = fmaxf(fmaf(si - q.y, -sg, 1.0f), 0.0f);
    if (fabsf(dr) >= 1.0f) { acc += t; cnt += 1.0f; }                  // NaN/tie -> false
}

__global__ void __launch_bounds__(THREADS) pairloss_kernel(
    const float* __restrict__ scores,
    const int* __restrict__ rankings,
    const uint8_t* __restrict__ mask,
    float* __restrict__ out,
    int B, int nblocks)
{
    // per row: entries 0..63 = elements, 64..95 = duplicate of elements 0..31
    __shared__ float2 sh[ROWS_PER_BLOCK][96];
    __shared__ float2 sh_row[ROWS_PER_BLOCK];
    __shared__ int s_last;

    const int lane = threadIdx.x & 31;
    const int w    = threadIdx.x >> 5;
    const int rA   = blockIdx.x * ROWS_PER_BLOCK + w * 2;   // first of this warp's two rows
    const int rB   = rA + 1;

    const float NaNf = __int_as_float(0x7fffffff);

    // ---- load both rows (12 LDGs issued up front) ----
    const int baseA = rA * H + lane;
    const int baseB = rB * H + lane;
    const float sA0 = scores[baseA];
    const float sA1 = scores[baseA + 32];
    const float sB0 = scores[baseB];
    const float sB1 = scores[baseB + 32];
    const int  rkA0 = rankings[baseA];
    const int  rkA1 = rankings[baseA + 32];
    const int  rkB0 = rankings[baseB];
    const int  rkB1 = rankings[baseB + 32];
    const bool vA0  = (mask[baseA] != 0)      && (rkA0 > 0);
    const bool vA1  = (mask[baseA + 32] != 0) && (rkA1 > 0);
    const bool vB0  = (mask[baseB] != 0)      && (rkB0 > 0);
    const bool vB1  = (mask[baseB + 32] != 0) && (rkB1 > 0);
    const float frA0 = vA0 ? (float)rkA0 : NaNf;
    const float frA1 = vA1 ? (float)rkA1 : NaNf;
    const float frB0 = vB0 ? (float)rkB0 : NaNf;
    const float frB1 = vB1 ? (float)rkB1 : NaNf;

    const int wa = w * 2, wb = w * 2 + 1;
    sh[wa][lane]      = make_float2(frA0, sA0);
    sh[wa][lane + 32] = make_float2(frA1, sA1);
    sh[wa][lane + 64] = make_float2(frA0, sA0);
    sh[wb][lane]      = make_float2(frB0, sB0);
    sh[wb][lane + 32] = make_float2(frB1, sB1);
    sh[wb][lane + 64] = make_float2(frB0, sB0);
    __syncwarp();

    float accA = 0.f, cntA = 0.f, accB = 0.f, cntB = 0.f;

    // distance-32 pairs (each owned by exactly one thread)
    pair_acc(frA0, sA0, make_float2(frA1, sA1), accA, cntA);
    pair_acc(frB0, sB0, make_float2(frB1, sB1), accB, cntB);

    const float2* rsa = sh[wa];
    const float2* rsb = sh[wb];
    #pragma unroll
    for (int k = 1; k <= 31; ++k) {
        const float2 qA0 = rsa[lane + k];
        const float2 qA1 = rsa[lane + 32 + k];
        const float2 qB0 = rsb[lane + k];
        const float2 qB1 = rsb[lane + 32 + k];
        pair_acc(frA0, sA0, qA0, accA, cntA);   // pair {lane, lane+k}        of row A
        pair_acc(frA1, sA1, qA1, accA, cntA);   // pair {lane+32, lane+32+k}  of row A
        pair_acc(frB0, sB0, qB0, accB, cntB);
        pair_acc(frB1, sB1, qB1, accB, cntB);
    }

    #pragma unroll
    for (int o = 16; o > 0; o >>= 1) {
        accA += __shfl_down_sync(0xffffffffu, accA, o);
        cntA += __shfl_down_sync(0xffffffffu, cntA, o);
        accB += __shfl_down_sync(0xffffffffu, accB, o);
        cntB += __shfl_down_sync(0xffffffffu, cntB, o);
    }
    if (lane == 0) {
        sh_row[wa] = make_float2((cntA > 0.f) ? (accA / cntA) : 0.f, (cntA > 0.f) ? 1.f : 0.f);
        sh_row[wb] = make_float2((cntB > 0.f) ? (accB / cntB) : 0.f, (cntB > 0.f) ? 1.f : 0.f);
    }
    __syncthreads();

    if (threadIdx.x == 0) {
        float l = 0.f, h = 0.f;
        #pragma unroll
        for (int i = 0; i < ROWS_PER_BLOCK; ++i) { l += sh_row[i].x; h += sh_row[i].y; }
        g_part[blockIdx.x] = make_float2(l, h);
        __threadfence();
        const unsigned int t = atomicAdd(&g_done, 1u);
        s_last = (t == (unsigned int)(nblocks - 1)) ? 1 : 0;
    }
    __syncthreads();

    // last block to finish reduces all partials in FIXED index order -> deterministic
    if (s_last) {
        __threadfence();
        float l = 0.f, h = 0.f;
        for (int i = threadIdx.x; i < nblocks; i += THREADS) {
            const float2 p = g_part[i];
            l += p.x;
            h += p.y;
        }
        // block reduce via shared
        __shared__ float f_l[THREADS];
        __shared__ float f_h[THREADS];
        f_l[threadIdx.x] = l;
        f_h[threadIdx.x] = h;
        __syncthreads();
        #pragma unroll
        for (int s = THREADS / 2; s > 0; s >>= 1) {
            if (threadIdx.x < s) {
                f_l[threadIdx.x] += f_l[threadIdx.x + s];
                f_h[threadIdx.x] += f_h[threadIdx.x + s];
            }
            __syncthreads();
        }
        if (threadIdx.x == 0) {
            const float n = f_h[0];
            out[0] = (n > 0.f) ? (f_l[0] / n) : 0.f;
            g_done = 0;                      // reset for next graph replay
        }
    }
}

extern "C" void kernel_launch(void* const* d_in, const int* in_sizes, int n_in,
                              void* d_out, int out_size)
{
    const float*   scores   = (const float*)d_in[0];
    const int*     rankings = (const int*)d_in[1];
    const uint8_t* mask     = (const uint8_t*)d_in[2];
    float*         out      = (float*)d_out;

    const int B = in_sizes[0] / H;
    const int nblocks = (B + ROWS_PER_BLOCK - 1) / ROWS_PER_BLOCK;

    pairloss_kernel<<<nblocks, THREADS>>>(scores, rankings, mask, out, B, nblocks);
}

// round 8
// speedup vs baseline: 1.4459x; 1.4459x over previous
#include <cuda_runtime.h>
#include <stdint.h>
#include <math.h>

#define H 64
#define RPB 8                 // rows per block, one warp per row
#define THREADS (RPB * 32)
#define MAXPART 4096

__device__ float2 g_part[MAXPART];
__device__ unsigned int g_done = 0;

__global__ void __launch_bounds__(THREADS) pairloss_kernel(
    const float* __restrict__ scores,
    const int* __restrict__ rankings,
    const uint8_t* __restrict__ mask,
    float* __restrict__ out,
    int B, int nblocks)
{
    // per row: entries 0..63 = elements, 64..95 = duplicate of elements 0..31
    __shared__ float2 sh[RPB][96];
    __shared__ float2 sh_row[RPB];
    __shared__ int s_last;

    const int lane = threadIdx.x & 31;
    const int w    = threadIdx.x >> 5;
    const int row  = blockIdx.x * RPB + w;

    const float NaNf = __int_as_float(0x7fffffff);

    const int base = row * H + lane;
    const float s0 = scores[base];
    const float s1 = scores[base + 32];
    const int   r0 = rankings[base];
    const int   r1 = rankings[base + 32];
    const bool  v0 = (mask[base] != 0)      && (r0 > 0);
    const bool  v1 = (mask[base + 32] != 0) && (r1 > 0);
    const float fr0 = v0 ? (float)r0 : NaNf;   // invalid -> NaN: all its pairs drop out
    const float fr1 = v1 ? (float)r1 : NaNf;

    sh[w][lane]      = make_float2(fr0, s0);
    sh[w][lane + 32] = make_float2(fr1, s1);
    sh[w][lane + 64] = make_float2(fr0, s0);   // duplicate for wrap-free indexing
    __syncwarp();

    float acc0 = 0.f, cnt0 = 0.f, acc1 = 0.f, cnt1 = 0.f;

    // held pair (lane, lane+32): circular distance 32, each owned by exactly one thread
    {
        const float dr = fr1 - fr0;
        const float sg = __int_as_float((__float_as_int(dr) & 0x80000000u) | 0x3f800000u);
        const float t  = fmaxf(fmaf(s0 - s1, -sg, 1.0f), 0.0f);
        if (fabsf(dr) >= 1.0f) { acc0 += t; cnt0 += 1.0f; }   // NaN/tie -> false
    }

    const float2* rowsh = sh[w];
    #pragma unroll
    for (int k = 1; k <= 31; ++k) {
        const float2 q0 = rowsh[lane + k];        // element (lane+k)            (no wrap)
        const float2 q1 = rowsh[lane + 32 + k];   // element (lane+32+k) mod 64 via duplicate
        // unordered pair {lane, lane+k}
        {
            const float dr = q0.x - fr0;
            const float sg = __int_as_float((__float_as_int(dr) & 0x80000000u) | 0x3f800000u);
            const float t  = fmaxf(fmaf(s0 - q0.y, -sg, 1.0f), 0.0f);
            if (fabsf(dr) >= 1.0f) { acc0 += t; cnt0 += 1.0f; }
        }
        // unordered pair {lane+32, (lane+32+k) mod 64}
        {
            const float dr = q1.x - fr1;
            const float sg = __int_as_float((__float_as_int(dr) & 0x80000000u) | 0x3f800000u);
            const float t  = fmaxf(fmaf(s1 - q1.y, -sg, 1.0f), 0.0f);
            if (fabsf(dr) >= 1.0f) { acc1 += t; cnt1 += 1.0f; }
        }
    }

    float acc = acc0 + acc1;
    float cnt = cnt0 + cnt1;
    #pragma unroll
    for (int o = 16; o > 0; o >>= 1) {
        acc += __shfl_down_sync(0xffffffffu, acc, o);
        cnt += __shfl_down_sync(0xffffffffu, cnt, o);
    }
    if (lane == 0) {
        sh_row[w] = make_float2((cnt > 0.f) ? (acc / cnt) : 0.f, (cnt > 0.f) ? 1.f : 0.f);
    }
    __syncthreads();

    if (threadIdx.x == 0) {
        float l = 0.f, h = 0.f;
        #pragma unroll
        for (int i = 0; i < RPB; ++i) { l += sh_row[i].x; h += sh_row[i].y; }
        g_part[blockIdx.x] = make_float2(l, h);
        __threadfence();
        const unsigned int t = atomicAdd(&g_done, 1u);
        s_last = (t == (unsigned int)(nblocks - 1)) ? 1 : 0;
    }
    __syncthreads();

    // last block to finish reduces all partials in FIXED index order -> deterministic
    if (s_last) {
        __threadfence();
        float l = 0.f, h = 0.f;
        for (int i = threadIdx.x; i < nblocks; i += THREADS) {
            const float2 p = g_part[i];
            l += p.x;
            h += p.y;
        }
        __shared__ float f_l[THREADS];
        __shared__ float f_h[THREADS];
        f_l[threadIdx.x] = l;
        f_h[threadIdx.x] = h;
        __syncthreads();
        #pragma unroll
        for (int s = THREADS / 2; s > 0; s >>= 1) {
            if (threadIdx.x < s) {
                f_l[threadIdx.x] += f_l[threadIdx.x + s];
                f_h[threadIdx.x] += f_h[threadIdx.x + s];
            }
            __syncthreads();
        }
        if (threadIdx.x == 0) {
            const float n = f_h[0];
            out[0] = (n > 0.f) ? (f_l[0] / n) : 0.f;
            g_done = 0;                      // reset for next graph replay
        }
    }
}

extern "C" void kernel_launch(void* const* d_in, const int* in_sizes, int n_in,
                              void* d_out, int out_size)
{
    const float*   scores   = (const float*)d_in[0];
    const int*     rankings = (const int*)d_in[1];
    const uint8_t* mask     = (const uint8_t*)d_in[2];
    float*         out      = (float*)d_out;

    const int B = in_sizes[0] / H;
    const int nblocks = (B + RPB - 1) / RPB;

    pairloss_kernel<<<nblocks, THREADS>>>(scores, rankings, mask, out, B, nblocks);
}

// round 9
// speedup vs baseline: 1.6212x; 1.1212x over previous
#include <cuda_runtime.h>
#include <stdint.h>
#include <math.h>

#define H 64
#define RPB 8                 // rows per block, one warp per row
#define THREADS (RPB * 32)
#define MAXPART 4096

__device__ float2 g_part[MAXPART];
__device__ unsigned int g_done = 0;

__device__ __forceinline__ unsigned long long addf32x2(unsigned long long a, unsigned long long b)
{
    unsigned long long r;
    asm("add.rn.f32x2 %0, %1, %2;" : "=l"(r) : "l"(a), "l"(b));
    return r;
}
__device__ __forceinline__ unsigned long long pk(float lo, float hi)
{
    unsigned long long r;
    asm("mov.b64 %0, {%1, %2};" : "=l"(r) : "f"(lo), "f"(hi));
    return r;
}
__device__ __forceinline__ void upk(unsigned long long v, float& lo, float& hi)
{
    asm("mov.b64 {%0, %1}, %2;" : "=f"(lo), "=f"(hi) : "l"(v));
}

__global__ void __launch_bounds__(THREADS) pairloss_kernel(
    const float* __restrict__ scores,
    const int* __restrict__ rankings,
    const uint8_t* __restrict__ mask,
    float* __restrict__ out,
    int B, int nblocks)
{
    // p[j] = (rank_j, rank_{(j+32)%64} | score_j, score_{(j+32)%64}), j = 0..63
    __shared__ ulonglong2 sh[RPB][64];
    __shared__ float2 sh_row[RPB];
    __shared__ int s_last;

    const int lane = threadIdx.x & 31;
    const int w    = threadIdx.x >> 5;
    const int row  = blockIdx.x * RPB + w;

    const float NaNf = __int_as_float(0x7fffffff);

    const int base = row * H + lane;
    const float s0 = scores[base];
    const float s1 = scores[base + 32];
    const int   r0 = rankings[base];
    const int   r1 = rankings[base + 32];
    const bool  v0 = (mask[base] != 0)      && (r0 > 0);
    const bool  v1 = (mask[base + 32] != 0) && (r1 > 0);
    const float fr0 = v0 ? (float)r0 : NaNf;   // invalid -> NaN rank: w gates its pairs to 0
    const float fr1 = v1 ? (float)r1 : NaNf;

    sh[w][lane]      = make_ulonglong2(pk(fr0, fr1), pk(s0, s1));
    sh[w][lane + 32] = make_ulonglong2(pk(fr1, fr0), pk(s1, s0));   // (j, j+32 mod 64) swapped
    __syncwarp();

    const unsigned long long negr2 = pk(-fr0, -fr1);   // -NaN is still NaN
    const unsigned long long negs2 = pk(-s0, -s1);

    float accL = 0.f, cntL = 0.f, accH = 0.f, cntH = 0.f;

    // distance-32 pair {lane, lane+32}: i=lane, j=lane+32
    {
        const float dr = fr1 - fr0;                 // NaN if either invalid
        const float u  = s1 - s0;                   // s_j - s_i  (finite)
        const float vv = __uint_as_float(__float_as_uint(u) ^ (__float_as_uint(dr) & 0x80000000u));
        const float t  = fmaxf(vv + 1.0f, 0.0f);    // finite even for NaN dr
        const float wt = __saturatef(fabsf(dr));    // 0 on tie/invalid(NaN), 1 otherwise
        accL = fmaf(t, wt, accL);
        cntL += wt;
    }

    const ulonglong2* rowsh = sh[w];
    #pragma unroll
    for (int k = 1; k <= 31; ++k) {
        const ulonglong2 q = rowsh[lane + k];                   // j = lane+k (<= 62)
        const unsigned long long dr2 = addf32x2(q.x, negr2);    // (r_j - r_i) both halves
        const unsigned long long u2  = addf32x2(q.y, negs2);    // (s_j - s_i) both halves
        float drl, drh, ul, uh;
        upk(dr2, drl, drh);
        upk(u2,  ul,  uh);
        // pair {lane, j}
        {
            const float vv = __uint_as_float(__float_as_uint(ul) ^ (__float_as_uint(drl) & 0x80000000u));
            const float t  = fmaxf(vv + 1.0f, 0.0f);
            const float wt = __saturatef(fabsf(drl));
            accL = fmaf(t, wt, accL);
            cntL += wt;
        }
        // pair {lane+32, (j+32) mod 64}
        {
            const float vv = __uint_as_float(__float_as_uint(uh) ^ (__float_as_uint(drh) & 0x80000000u));
            const float t  = fmaxf(vv + 1.0f, 0.0f);
            const float wt = __saturatef(fabsf(drh));
            accH = fmaf(t, wt, accH);
            cntH += wt;
        }
    }

    float acc = accL + accH;
    float cnt = cntL + cntH;
    #pragma unroll
    for (int o = 16; o > 0; o >>= 1) {
        acc += __shfl_down_sync(0xffffffffu, acc, o);
        cnt += __shfl_down_sync(0xffffffffu, cnt, o);
    }
    if (lane == 0) {
        sh_row[w] = make_float2((cnt > 0.f) ? (acc / cnt) : 0.f, (cnt > 0.f) ? 1.f : 0.f);
    }
    __syncthreads();

    if (threadIdx.x == 0) {
        float l = 0.f, h = 0.f;
        #pragma unroll
        for (int i = 0; i < RPB; ++i) { l += sh_row[i].x; h += sh_row[i].y; }
        g_part[blockIdx.x] = make_float2(l, h);
        __threadfence();
        const unsigned int t = atomicAdd(&g_done, 1u);
        s_last = (t == (unsigned int)(nblocks - 1)) ? 1 : 0;
    }
    __syncthreads();

    // last block reduces all partials in FIXED index order -> deterministic
    if (s_last) {
        __threadfence();
        float l = 0.f, h = 0.f;
        for (int i = threadIdx.x; i < nblocks; i += THREADS) {
            const float2 p = g_part[i];
            l += p.x;
            h += p.y;
        }
        __shared__ float f_l[THREADS];
        __shared__ float f_h[THREADS];
        f_l[threadIdx.x] = l;
        f_h[threadIdx.x] = h;
        __syncthreads();
        #pragma unroll
        for (int s = THREADS / 2; s > 0; s >>= 1) {
            if (threadIdx.x < s) {
                f_l[threadIdx.x] += f_l[threadIdx.x + s];
                f_h[threadIdx.x] += f_h[threadIdx.x + s];
            }
            __syncthreads();
        }
        if (threadIdx.x == 0) {
            const float n = f_h[0];
            out[0] = (n > 0.f) ? (f_l[0] / n) : 0.f;
            g_done = 0;                      // reset for next graph replay
        }
    }
}

extern "C" void kernel_launch(void* const* d_in, const int* in_sizes, int n_in,
                              void* d_out, int out_size)
{
    const float*   scores   = (const float*)d_in[0];
    const int*     rankings = (const int*)d_in[1];
    const uint8_t* mask     = (const uint8_t*)d_in[2];
    float*         out      = (float*)d_out;

    const int B = in_sizes[0] / H;
    const int nblocks = (B + RPB - 1) / RPB;

    pairloss_kernel<<<nblocks, THREADS>>>(scores, rankings, mask, out, B, nblocks);
}

// round 10
// speedup vs baseline: 1.6243x; 1.0019x over previous
#include <cuda_runtime.h>
#include <stdint.h>
#include <math.h>

#define H 64
#define WARPS 8
#define BATCHES 2                      // rows per warp, sequential
#define ROWS_PER_BLOCK (WARPS * BATCHES)
#define THREADS (WARPS * 32)
#define MAXPART 2048

__device__ float2 g_part[MAXPART];
__device__ unsigned int g_done = 0;

__device__ __forceinline__ unsigned long long addf32x2(unsigned long long a, unsigned long long b)
{
    unsigned long long r;
    asm("add.rn.f32x2 %0, %1, %2;" : "=l"(r) : "l"(a), "l"(b));
    return r;
}
__device__ __forceinline__ unsigned long long pk(float lo, float hi)
{
    unsigned long long r;
    asm("mov.b64 %0, {%1, %2};" : "=l"(r) : "f"(lo), "f"(hi));
    return r;
}
__device__ __forceinline__ void upk(unsigned long long v, float& lo, float& hi)
{
    asm("mov.b64 {%0, %1}, %2;" : "=f"(lo), "=f"(hi) : "l"(v));
}

__global__ void __launch_bounds__(THREADS) pairloss_kernel(
    const float* __restrict__ scores,
    const int* __restrict__ rankings,
    const uint8_t* __restrict__ mask,
    float* __restrict__ out,
    int B, int nblocks)
{
    // per warp: p[j] = (rank_j, rank_{(j+32)%64} | score_j, score_{(j+32)%64})
    __shared__ ulonglong2 sh[WARPS][64];
    __shared__ float2 sh_row[ROWS_PER_BLOCK];
    __shared__ int s_last;

    const int lane = threadIdx.x & 31;
    const int w    = threadIdx.x >> 5;

    const float NaNf = __int_as_float(0x7fffffff);

    #pragma unroll
    for (int b = 0; b < BATCHES; ++b) {
        const int row = blockIdx.x * ROWS_PER_BLOCK + b * WARPS + w;

        const int base = row * H + lane;
        const float s0 = scores[base];
        const float s1 = scores[base + 32];
        const int   r0 = rankings[base];
        const int   r1 = rankings[base + 32];
        const bool  v0 = (mask[base] != 0)      && (r0 > 0);
        const bool  v1 = (mask[base + 32] != 0) && (r1 > 0);
        const float fr0 = v0 ? (float)r0 : NaNf;   // invalid -> NaN rank: gates its pairs to 0
        const float fr1 = v1 ? (float)r1 : NaNf;

        __syncwarp();                              // batch>0: all lanes done reading old tile
        sh[w][lane]      = make_ulonglong2(pk(fr0, fr1), pk(s0, s1));
        sh[w][lane + 32] = make_ulonglong2(pk(fr1, fr0), pk(s1, s0));  // (j, j+32 mod 64) swapped
        __syncwarp();

        const unsigned long long negr2 = pk(-fr0, -fr1);   // -NaN is still NaN
        const unsigned long long negs2 = pk(-s0, -s1);

        float accL = 0.f, cntL = 0.f, accH = 0.f, cntH = 0.f;

        // distance-32 pair {lane, lane+32}
        {
            const float dr = fr1 - fr0;
            const float u  = s1 - s0;
            const float vv = __uint_as_float(__float_as_uint(u) ^ (__float_as_uint(dr) & 0x80000000u));
            const float t  = fmaxf(vv + 1.0f, 0.0f);
            const float wt = __saturatef(fabsf(dr));       // 0 on tie/invalid(NaN), 1 otherwise
            accL = fmaf(t, wt, accL);
            cntL += wt;
        }

        const ulonglong2* rowsh = sh[w];
        #pragma unroll
        for (int k = 1; k <= 31; ++k) {
            const ulonglong2 q = rowsh[lane + k];                   // j = lane+k (<= 62)
            const unsigned long long dr2 = addf32x2(q.x, negr2);    // (r_j - r_i) both halves
            const unsigned long long u2  = addf32x2(q.y, negs2);    // (s_j - s_i) both halves
            float drl, drh, ul, uh;
            upk(dr2, drl, drh);
            upk(u2,  ul,  uh);
            // pair {lane, j}
            {
                const float vv = __uint_as_float(__float_as_uint(ul) ^ (__float_as_uint(drl) & 0x80000000u));
                const float t  = fmaxf(vv + 1.0f, 0.0f);
                const float wt = __saturatef(fabsf(drl));
                accL = fmaf(t, wt, accL);
                cntL += wt;
            }
            // pair {lane+32, (j+32) mod 64}
            {
                const float vv = __uint_as_float(__float_as_uint(uh) ^ (__float_as_uint(drh) & 0x80000000u));
                const float t  = fmaxf(vv + 1.0f, 0.0f);
                const float wt = __saturatef(fabsf(drh));
                accH = fmaf(t, wt, accH);
                cntH += wt;
            }
        }

        float acc = accL + accH;
        float cnt = cntL + cntH;
        #pragma unroll
        for (int o = 16; o > 0; o >>= 1) {
            acc += __shfl_down_sync(0xffffffffu, acc, o);
            cnt += __shfl_down_sync(0xffffffffu, cnt, o);
        }
        if (lane == 0) {
            sh_row[b * WARPS + w] =
                make_float2((cnt > 0.f) ? (acc / cnt) : 0.f, (cnt > 0.f) ? 1.f : 0.f);
        }
    }
    __syncthreads();

    if (threadIdx.x == 0) {
        float l = 0.f, h = 0.f;
        #pragma unroll
        for (int i = 0; i < ROWS_PER_BLOCK; ++i) { l += sh_row[i].x; h += sh_row[i].y; }
        g_part[blockIdx.x] = make_float2(l, h);
        __threadfence();
        const unsigned int t = atomicAdd(&g_done, 1u);
        s_last = (t == (unsigned int)(nblocks - 1)) ? 1 : 0;
    }
    __syncthreads();

    // last block reduces all partials in FIXED index order -> deterministic
    if (s_last) {
        __threadfence();
        float l = 0.f, h = 0.f;
        for (int i = threadIdx.x; i < nblocks; i += THREADS) {
            const float2 p = g_part[i];
            l += p.x;
            h += p.y;
        }
        __shared__ float f_l[THREADS];
        __shared__ float f_h[THREADS];
        f_l[threadIdx.x] = l;
        f_h[threadIdx.x] = h;
        __syncthreads();
        #pragma unroll
        for (int s = THREADS / 2; s > 0; s >>= 1) {
            if (threadIdx.x < s) {
                f_l[threadIdx.x] += f_l[threadIdx.x + s];
                f_h[threadIdx.x] += f_h[threadIdx.x + s];
            }
            __syncthreads();
        }
        if (threadIdx.x == 0) {
            const float n = f_h[0];
            out[0] = (n > 0.f) ? (f_l[0] / n) : 0.f;
            g_done = 0;                      // reset for next graph replay
        }
    }
}

extern "C" void kernel_launch(void* const* d_in, const int* in_sizes, int n_in,
                              void* d_out, int out_size)
{
    const float*   scores   = (const float*)d_in[0];
    const int*     rankings = (const int*)d_in[1];
    const uint8_t* mask     = (const uint8_t*)d_in[2];
    float*         out      = (float*)d_out;

    const int B = in_sizes[0] / H;
    const int nblocks = (B + ROWS_PER_BLOCK - 1) / ROWS_PER_BLOCK;

    pairloss_kernel<<<nblocks, THREADS>>>(scores, rankings, mask, out, B, nblocks);
}